// round 15
// baseline (speedup 1.0000x reference)
#include <cuda_runtime.h>
#include <cuda_bf16.h>

#define D_MODEL 1024
#define MAX_SEGS 256
#define NTHREADS 256
#define NBLOCKS  1184        // 8 * 148
#define TILE 8

__device__ float g_seg_sum[MAX_SEGS];              // zero-init at load; norm re-zeroes
__device__ float g_scratch[MAX_SEGS * D_MODEL];    // zero-init at load; norm re-zeroes

// ---------------------------------------------------------------------------
// Main kernel: CTA-per-token-range, 8-token tiles.  (R5/R13 shape, verbatim.)
// Thread tid owns dims [4*tid, 4*tid+4). 8 float4 loads in flight per thread;
// 2 __syncthreads per 8 tokens; 8 shfl-reduces pipelined.
// ---------------------------------------------------------------------------
__global__ __launch_bounds__(NTHREADS)
void pool_kernel(const float* __restrict__ x,
                 const int*   __restrict__ cu,
                 const float* __restrict__ Wp,
                 const float* __restrict__ bp,
                 int T, int nseg) {
    __shared__ float s_part[8][TILE];   // [warp][token]
    __shared__ float s_p[TILE];
    __shared__ int   s_cu[MAX_SEGS + 1];

    const int tid  = threadIdx.x;
    const int lane = tid & 31;
    const int wid  = tid >> 5;

    if (tid <= nseg) s_cu[tid] = cu[tid];

    const float4 w = *reinterpret_cast<const float4*>(Wp + tid * 4);
    const float  b = bp[0];

    const int per = (T + NBLOCKS - 1) / NBLOCKS;
    const int t0  = blockIdx.x * per;
    const int t1  = min(t0 + per, T);
    __syncthreads();
    if (t0 >= t1) return;

    int seg = 0;
    while (s_cu[seg + 1] <= t0) seg++;
    int nb = s_cu[seg + 1];

    float4 acc = make_float4(0.f, 0.f, 0.f, 0.f);
    float  sump = 0.0f;

    const float4* xv = reinterpret_cast<const float4*>(x);

#define FLUSH()                                                            \
    do {                                                                   \
        float* o = g_scratch + (size_t)seg * D_MODEL + tid * 4;            \
        atomicAdd(o + 0, acc.x);  atomicAdd(o + 1, acc.y);                 \
        atomicAdd(o + 2, acc.z);  atomicAdd(o + 3, acc.w);                 \
        if (tid == 0) atomicAdd(&g_seg_sum[seg], sump);                    \
    } while (0)

    for (int t = t0; t < t1; t += TILE) {
        const int nvalid = min(TILE, t1 - t);

        // ---- Phase 1: load 8 rows (8 independent LDG.128 per thread) ----
        float4 v[TILE];
#pragma unroll
        for (int j = 0; j < TILE; j++) {
            if (j < nvalid) v[j] = xv[(size_t)(t + j) * 256 + tid];
            else            v[j] = make_float4(0.f, 0.f, 0.f, 0.f);
        }

        // ---- Phase 2: 8 partial dots, pipelined warp reduce ----
        float d[TILE];
#pragma unroll
        for (int j = 0; j < TILE; j++)
            d[j] = v[j].x * w.x + v[j].y * w.y + v[j].z * w.z + v[j].w * w.w;
#pragma unroll
        for (int o = 16; o > 0; o >>= 1) {
#pragma unroll
            for (int j = 0; j < TILE; j++)
                d[j] += __shfl_xor_sync(0xffffffffu, d[j], o);
        }
        if (lane == 0) {
#pragma unroll
            for (int j = 0; j < TILE; j++) s_part[wid][j] = d[j];
        }
        __syncthreads();

        // ---- Phase 3: warp 0 finishes 8 block-sums + exps ----
        if (wid == 0 && lane < TILE) {
            float s = 0.0f;
#pragma unroll
            for (int ww = 0; ww < 8; ww++) s += s_part[ww][lane];
            s_p[lane] = __expf(s + b);   // unshifted exp: |score| <~ 6
        }
        __syncthreads();

        // ---- Phase 4: accumulate, with rare segment-boundary flushes ----
#pragma unroll
        for (int j = 0; j < TILE; j++) {
            const int tt = t + j;
            if (j >= nvalid) break;
            if (tt >= nb) {              // rare: 63 crossings / 16K tiles
                FLUSH();
                acc = make_float4(0.f, 0.f, 0.f, 0.f);  sump = 0.0f;
                do { seg++; nb = s_cu[seg + 1]; } while (tt >= nb);
            }
            const float p = s_p[j];
            sump += p;
            acc.x += p * v[j].x;  acc.y += p * v[j].y;
            acc.z += p * v[j].z;  acc.w += p * v[j].w;
        }
    }
    FLUSH();
#undef FLUSH
}

// ---------------------------------------------------------------------------
// Norm kernel (PDL secondary): launched with programmatic stream
// serialization so its CTAs come up DURING pool execution; the grid
// dependency sync blocks until pool's writes (atomics included) are visible.
// Then: read scratch+sum, write out, re-zero state for the next graph replay.
// ---------------------------------------------------------------------------
__global__ void norm_kernel(float* __restrict__ out) {
    cudaGridDependencySynchronize();

    const int s   = blockIdx.x;
    const int tid = threadIdx.x;
    const float inv = 1.0f / g_seg_sum[s];

    float4* sc = reinterpret_cast<float4*>(g_scratch + (size_t)s * D_MODEL);
    float4* o  = reinterpret_cast<float4*>(out       + (size_t)s * D_MODEL);

    const float4 v = sc[tid];
    o[tid]  = make_float4(v.x * inv, v.y * inv, v.z * inv, v.w * inv);
    sc[tid] = make_float4(0.f, 0.f, 0.f, 0.f);
    __syncthreads();
    if (tid == 0) g_seg_sum[s] = 0.0f;
}

// ---------------------------------------------------------------------------
extern "C" void kernel_launch(void* const* d_in, const int* in_sizes, int n_in,
                              void* d_out, int out_size) {
    const float* x  = (const float*)d_in[0];
    const int*   cu = (const int*)  d_in[1];
    const float* W  = (const float*)d_in[2];
    const float* b  = (const float*)d_in[3];
    float* out = (float*)d_out;

    const int T    = in_sizes[0] / D_MODEL;
    const int nseg = in_sizes[1] - 1;

    pool_kernel<<<NBLOCKS, NTHREADS>>>(x, cu, W, b, T, nseg);

    // PDL launch of the epilogue: overlaps its launch/ramp with pool's tail.
    cudaLaunchConfig_t cfg = {};
    cfg.gridDim  = dim3((unsigned)nseg, 1, 1);
    cfg.blockDim = dim3(NTHREADS, 1, 1);
    cudaLaunchAttribute attr[1];
    attr[0].id = cudaLaunchAttributeProgrammaticStreamSerialization;
    attr[0].val.programmaticStreamSerializationAllowed = 1;
    cfg.attrs    = attr;
    cfg.numAttrs = 1;
    cudaLaunchKernelEx(&cfg, norm_kernel, out);
}

// round 16
// speedup vs baseline: 1.0004x; 1.0004x over previous
#include <cuda_runtime.h>
#include <cuda_bf16.h>

#define D_MODEL 1024
#define MAX_SEGS 256
#define NTHREADS 256
#define NBLOCKS  1184        // 8 * 148
#define TILE 8

__device__ float g_seg_sum[MAX_SEGS];              // zero-init at load; norm re-zeroes
__device__ float g_scratch[MAX_SEGS * D_MODEL];    // zero-init at load; norm re-zeroes

// ---------------------------------------------------------------------------
// Main kernel: CTA-per-token-range, 8-token tiles.  (R5/R13 shape, verbatim,
// plus a PDL trigger at CTA start.)
// Thread tid owns dims [4*tid, 4*tid+4). 8 float4 loads in flight per thread;
// 2 __syncthreads per 8 tokens; 8 shfl-reduces pipelined.
// ---------------------------------------------------------------------------
__global__ __launch_bounds__(NTHREADS)
void pool_kernel(const float* __restrict__ x,
                 const int*   __restrict__ cu,
                 const float* __restrict__ Wp,
                 const float* __restrict__ bp,
                 int T, int nseg) {
    // PDL: count this CTA toward the secondary's launch trigger. Fires once
    // all CTAs have started (i.e., when the last wave begins), so the norm
    // kernel's grid comes up and parks in its dependency-sync during pool's
    // tail instead of serializing its launch ramp after pool.
    cudaTriggerProgrammaticLaunchCompletion();

    __shared__ float s_part[8][TILE];   // [warp][token]
    __shared__ float s_p[TILE];
    __shared__ int   s_cu[MAX_SEGS + 1];

    const int tid  = threadIdx.x;
    const int lane = tid & 31;
    const int wid  = tid >> 5;

    if (tid <= nseg) s_cu[tid] = cu[tid];

    const float4 w = *reinterpret_cast<const float4*>(Wp + tid * 4);
    const float  b = bp[0];

    const int per = (T + NBLOCKS - 1) / NBLOCKS;
    const int t0  = blockIdx.x * per;
    const int t1  = min(t0 + per, T);
    __syncthreads();
    if (t0 >= t1) return;

    int seg = 0;
    while (s_cu[seg + 1] <= t0) seg++;
    int nb = s_cu[seg + 1];

    float4 acc = make_float4(0.f, 0.f, 0.f, 0.f);
    float  sump = 0.0f;

    const float4* xv = reinterpret_cast<const float4*>(x);

#define FLUSH()                                                            \
    do {                                                                   \
        float* o = g_scratch + (size_t)seg * D_MODEL + tid * 4;            \
        atomicAdd(o + 0, acc.x);  atomicAdd(o + 1, acc.y);                 \
        atomicAdd(o + 2, acc.z);  atomicAdd(o + 3, acc.w);                 \
        if (tid == 0) atomicAdd(&g_seg_sum[seg], sump);                    \
    } while (0)

    for (int t = t0; t < t1; t += TILE) {
        const int nvalid = min(TILE, t1 - t);

        // ---- Phase 1: load 8 rows (8 independent LDG.128 per thread) ----
        float4 v[TILE];
#pragma unroll
        for (int j = 0; j < TILE; j++) {
            if (j < nvalid) v[j] = xv[(size_t)(t + j) * 256 + tid];
            else            v[j] = make_float4(0.f, 0.f, 0.f, 0.f);
        }

        // ---- Phase 2: 8 partial dots, pipelined warp reduce ----
        float d[TILE];
#pragma unroll
        for (int j = 0; j < TILE; j++)
            d[j] = v[j].x * w.x + v[j].y * w.y + v[j].z * w.z + v[j].w * w.w;
#pragma unroll
        for (int o = 16; o > 0; o >>= 1) {
#pragma unroll
            for (int j = 0; j < TILE; j++)
                d[j] += __shfl_xor_sync(0xffffffffu, d[j], o);
        }
        if (lane == 0) {
#pragma unroll
            for (int j = 0; j < TILE; j++) s_part[wid][j] = d[j];
        }
        __syncthreads();

        // ---- Phase 3: warp 0 finishes 8 block-sums + exps ----
        if (wid == 0 && lane < TILE) {
            float s = 0.0f;
#pragma unroll
            for (int ww = 0; ww < 8; ww++) s += s_part[ww][lane];
            s_p[lane] = __expf(s + b);   // unshifted exp: |score| <~ 6
        }
        __syncthreads();

        // ---- Phase 4: accumulate, with rare segment-boundary flushes ----
#pragma unroll
        for (int j = 0; j < TILE; j++) {
            const int tt = t + j;
            if (j >= nvalid) break;
            if (tt >= nb) {              // rare: 63 crossings / 16K tiles
                FLUSH();
                acc = make_float4(0.f, 0.f, 0.f, 0.f);  sump = 0.0f;
                do { seg++; nb = s_cu[seg + 1]; } while (tt >= nb);
            }
            const float p = s_p[j];
            sump += p;
            acc.x += p * v[j].x;  acc.y += p * v[j].y;
            acc.z += p * v[j].z;  acc.w += p * v[j].w;
        }
    }
    FLUSH();
#undef FLUSH
}

// ---------------------------------------------------------------------------
// Norm kernel (PDL secondary): its grid launches while pool's last wave runs,
// parks in the dependency sync (hardware wait), and proceeds the instant
// pool's writes (atomics included) are visible.
// Then: read scratch+sum, write out, re-zero state for the next graph replay.
// ---------------------------------------------------------------------------
__global__ void norm_kernel(float* __restrict__ out) {
    cudaGridDependencySynchronize();

    const int s   = blockIdx.x;
    const int tid = threadIdx.x;
    const float inv = 1.0f / g_seg_sum[s];

    float4* sc = reinterpret_cast<float4*>(g_scratch + (size_t)s * D_MODEL);
    float4* o  = reinterpret_cast<float4*>(out       + (size_t)s * D_MODEL);

    const float4 v = sc[tid];
    o[tid]  = make_float4(v.x * inv, v.y * inv, v.z * inv, v.w * inv);
    sc[tid] = make_float4(0.f, 0.f, 0.f, 0.f);
    __syncthreads();
    if (tid == 0) g_seg_sum[s] = 0.0f;
}

// ---------------------------------------------------------------------------
extern "C" void kernel_launch(void* const* d_in, const int* in_sizes, int n_in,
                              void* d_out, int out_size) {
    const float* x  = (const float*)d_in[0];
    const int*   cu = (const int*)  d_in[1];
    const float* W  = (const float*)d_in[2];
    const float* b  = (const float*)d_in[3];
    float* out = (float*)d_out;

    const int T    = in_sizes[0] / D_MODEL;
    const int nseg = in_sizes[1] - 1;

    pool_kernel<<<NBLOCKS, NTHREADS>>>(x, cu, W, b, T, nseg);

    // PDL launch of the epilogue: overlaps its launch/ramp with pool's tail.
    cudaLaunchConfig_t cfg = {};
    cfg.gridDim  = dim3((unsigned)nseg, 1, 1);
    cfg.blockDim = dim3(NTHREADS, 1, 1);
    cudaLaunchAttribute attr[1];
    attr[0].id = cudaLaunchAttributeProgrammaticStreamSerialization;
    attr[0].val.programmaticStreamSerializationAllowed = 1;
    cfg.attrs    = attr;
    cfg.numAttrs = 1;
    cudaLaunchKernelEx(&cfg, norm_kernel, out);
}